// round 9
// baseline (speedup 1.0000x reference)
#include <cuda_runtime.h>

// FINAL KERNEL — session converged at the launch/graph-replay floor.
//
// Reference analysis (verified rel_err == 0.0 on all 8 rounds):
//   The reference ends with softmax(d, axis=-1) where d has last dim == 1.
//   Softmax over a size-1 axis is identically 1.0 (exp(x-x)/exp(x-x)), so
//   out[b,t] = sigmoid(1.0) = 0.7310585786300049 for every (b,t),
//   independent of all inputs, the LSTM, and the attention.
//   The output is a constant (64, 512) fp32 tensor -> optimal kernel is a
//   128 KB coalesced fill.
//
// Session evidence (8 rounds):
//   - This config (64x128, 1 predicated STG.128/thread): 4.608, 4.768, 4.608 us
//     (best and most repeatable; kernel dur 3.42-3.68us = pure launch overhead,
//     issue <= 4%, DRAM 0.0%, 16 regs).
//   - Other grid shapes / instruction counts: neutral (4.83us +/- noise).
//   - Copy-engine memcpy node: worse mean (5.04) and 4x variance; rejected on
//     confirmation re-bench.
// Remaining time is harness-owned launch + graph-replay overhead. Closed.

static constexpr float SIGMOID_ONE = 0.73105857863000487925f; // 1/(1+exp(-1))

__global__ void __launch_bounds__(128, 1)
AttentionRNNLayer_87677462380995_kernel(float4* __restrict__ out4, int n4) {
    int i = blockIdx.x * blockDim.x + threadIdx.x;
    if (i < n4) {
        out4[i] = make_float4(SIGMOID_ONE, SIGMOID_ONE, SIGMOID_ONE, SIGMOID_ONE);
    }
}

extern "C" void kernel_launch(void* const* d_in, const int* in_sizes, int n_in,
                              void* d_out, int out_size) {
    (void)d_in; (void)in_sizes; (void)n_in;
    // out_size = 32768 fp32 = 8192 float4 stores; one coalesced STG.128 per thread.
    int n4 = out_size >> 2;                     // 8192
    int threads = 128;
    int blocks = (n4 + threads - 1) / threads;  // 64
    AttentionRNNLayer_87677462380995_kernel<<<blocks, threads>>>(
        reinterpret_cast<float4*>(d_out), n4);
}

// round 10
// speedup vs baseline: 1.3333x; 1.3333x over previous
#include <cuda_runtime.h>

// FINAL KERNEL — holding the converged configuration (R9's 6.1us reading was
// harness-side noise: ncu showed the kernel itself at a dead-normal 3.648us
// with identical metrics to every prior profile).
//
// Reference analysis (verified rel_err == 0.0 on all 9 rounds):
//   The reference ends with softmax(d, axis=-1) where d has last dim == 1.
//   Softmax over a size-1 axis is identically 1.0 (exp(x-x)/exp(x-x)), so
//   out[b,t] = sigmoid(1.0) = 0.7310585786300049 for every (b,t),
//   independent of all inputs, the LSTM, and the attention.
//   The output is a constant (64, 512) fp32 tensor -> 128 KB coalesced fill.
//
// Session evidence (9 rounds):
//   - This config (64x128, 1 predicated STG.128/thread), 4 runs:
//       bench 4.608, 4.768, 4.608, 6.144(outlier) us;
//       kernel dur 3.42-3.68us every time (issue <= 4%, DRAM 0.0%, 16 regs).
//   - Other grid shapes / instruction counts: neutral.
//   - Copy-engine memcpy node: worse mean + 4x variance; rejected.
// Kernel-side time is deterministic launch overhead; residual bench variance
// is harness-owned replay/measurement jitter. Nothing in this file can move it.

static constexpr float SIGMOID_ONE = 0.73105857863000487925f; // 1/(1+exp(-1))

__global__ void __launch_bounds__(128, 1)
AttentionRNNLayer_87677462380995_kernel(float4* __restrict__ out4, int n4) {
    int i = blockIdx.x * blockDim.x + threadIdx.x;
    if (i < n4) {
        out4[i] = make_float4(SIGMOID_ONE, SIGMOID_ONE, SIGMOID_ONE, SIGMOID_ONE);
    }
}

extern "C" void kernel_launch(void* const* d_in, const int* in_sizes, int n_in,
                              void* d_out, int out_size) {
    (void)d_in; (void)in_sizes; (void)n_in;
    // out_size = 32768 fp32 = 8192 float4 stores; one coalesced STG.128 per thread.
    int n4 = out_size >> 2;                     // 8192
    int threads = 128;
    int blocks = (n4 + threads - 1) / threads;  // 64
    AttentionRNNLayer_87677462380995_kernel<<<blocks, threads>>>(
        reinterpret_cast<float4*>(d_out), n4);
}